// round 9
// baseline (speedup 1.0000x reference)
#include <cuda_runtime.h>
#include <cuda_bf16.h>
#include <cstdint>

#define NN 50000
#define NE 800000
#define DD 128

#define BM 64          // rows per block
#define ASTRIDE 132    // b32 per A-tile row (128 bf16-pairs + 4 pad)
#define BSTRIDE 12     // b32 per B-tile row (8 pairs + 4 pad)
// dynamic SMEM: A(H,L) + B(2 bufs x H,L)
#define SMEM_B32  (2 * BM * ASTRIDE + 4 * 128 * BSTRIDE)
#define SMEM_BYTES (SMEM_B32 * 4)

// ---------------- scratch (static device globals; no allocation) ----------------
__device__ int   g_is64;
__device__ int   g_total;
__device__ int   g_deg[NN];
__device__ int   g_off[NN];
__device__ int   g_cur[NN];
__device__ float g_invdeg[NN];
__device__ int   g_col[NE];
__device__ float g_h1 [(size_t)NN * DD];
__device__ float g_h2 [(size_t)NN * DD];

__device__ __forceinline__ const float* sel_in(int sel, const float* x) {
    return sel == 0 ? x : (sel == 1 ? (const float*)g_h1 : (const float*)g_h2);
}
__device__ __forceinline__ int get_src(const int* __restrict__ ei, int e) {
    return g_is64 ? ei[2 * e] : ei[e];
}
__device__ __forceinline__ int get_dst(const int* __restrict__ ei, int e) {
    return g_is64 ? ei[2 * NE + 2 * e] : ei[NE + e];
}

// Split a float pair into bf16-hi pair (packed b32) and bf16-lo residual pair.
__device__ __forceinline__ uint32_t pack_hi_lo(float a, float b, uint32_t* lo) {
    __nv_bfloat16 ha = __float2bfloat16_rn(a);
    __nv_bfloat16 hb = __float2bfloat16_rn(b);
    __nv_bfloat16 la = __float2bfloat16_rn(a - __bfloat162float(ha));
    __nv_bfloat16 lb = __float2bfloat16_rn(b - __bfloat162float(hb));
    *lo = ((uint32_t)__bfloat16_as_ushort(lb) << 16) | __bfloat16_as_ushort(la);
    return ((uint32_t)__bfloat16_as_ushort(hb) << 16) | __bfloat16_as_ushort(ha);
}

__device__ __forceinline__ void mma16816(float* d, const uint32_t* a, uint32_t b0, uint32_t b1) {
    asm volatile(
        "mma.sync.aligned.m16n8k16.row.col.f32.bf16.bf16.f32 "
        "{%0,%1,%2,%3}, {%4,%5,%6,%7}, {%8,%9}, {%0,%1,%2,%3};"
        : "+f"(d[0]), "+f"(d[1]), "+f"(d[2]), "+f"(d[3])
        : "r"(a[0]), "r"(a[1]), "r"(a[2]), "r"(a[3]), "r"(b0), "r"(b1));
}

// ---------------- dtype detection ----------------
__global__ void k_detect(const int* __restrict__ ei) {
    if (threadIdx.x == 0 && blockIdx.x == 0) {
        int acc = 0;
        for (int i = 1; i < 512; i += 2) acc |= ei[i];
        g_is64 = (acc == 0) ? 1 : 0;
    }
}

// ---------------- CSR build ----------------
__global__ void k_zero_deg() {
    int i = blockIdx.x * blockDim.x + threadIdx.x;
    if (i < NN) g_deg[i] = 0;
    if (i == 0) g_total = 0;
}
__global__ void k_hist(const int* __restrict__ ei) {
    int e = blockIdx.x * blockDim.x + threadIdx.x;
    if (e < NE) {
        int d = get_dst(ei, e);
        if ((unsigned)d < NN) atomicAdd(&g_deg[d], 1);
    }
}
__global__ __launch_bounds__(256) void k_alloc() {
    __shared__ int warp_sums[8];
    __shared__ int block_base;
    int i = blockIdx.x * 256 + threadIdx.x;
    int lane = threadIdx.x & 31;
    int wid  = threadIdx.x >> 5;
    int d = (i < NN) ? g_deg[i] : 0;
    int sc = d;
#pragma unroll
    for (int o = 1; o < 32; o <<= 1) {
        int v = __shfl_up_sync(0xffffffffu, sc, o);
        if (lane >= o) sc += v;
    }
    if (lane == 31) warp_sums[wid] = sc;
    __syncthreads();
    if (wid == 0) {
        int ws = (lane < 8) ? warp_sums[lane] : 0;
#pragma unroll
        for (int o = 1; o < 8; o <<= 1) {
            int v = __shfl_up_sync(0xffffffffu, ws, o);
            if (lane >= o) ws += v;
        }
        if (lane < 8) warp_sums[lane] = ws;
        if (lane == 7) block_base = atomicAdd(&g_total, ws);
    }
    __syncthreads();
    if (i < NN) {
        int excl = sc - d + (wid > 0 ? warp_sums[wid - 1] : 0) + block_base;
        g_off[i] = excl;
        g_cur[i] = excl;
        g_invdeg[i] = 1.0f / (float)(d > 0 ? d : 1);
    }
}
__global__ void k_fill(const int* __restrict__ ei) {
    int e = blockIdx.x * blockDim.x + threadIdx.x;
    if (e < NE) {
        int d = get_dst(ei, e);
        int s = get_src(ei, e);
        if ((unsigned)d < NN && (unsigned)s < NN) {
            int p = atomicAdd(&g_cur[d], 1);
            g_col[p] = s;
        }
    }
}

// ---------------- fused aggregate + HMMA bf16-split GEMM -----------------------
// Per block: 64 output rows x 128 cols.
// Phase 1: aggregate 64 nodes into SMEM A-tile (K cols 0..127) + own features
//          (K cols 128..255), as bf16 hi/lo pairs.
// Phase 2: out = [agg|h] @ [Wl;Wr]^T + b (+relu), 16 K-chunks of 16,
//          B (weights) double-buffered, split products AhBh + AhBl + AlBh.
__global__ __launch_bounds__(512) void k_fused(int in_sel, const float* __restrict__ x,
                                               const float* __restrict__ Wl,
                                               const float* __restrict__ bl,
                                               const float* __restrict__ Wr,
                                               int out_sel, float* __restrict__ ext_out,
                                               int relu) {
    extern __shared__ uint32_t sm[];
    uint32_t* AsH = sm;                          // [BM][ASTRIDE]
    uint32_t* AsL = sm + BM * ASTRIDE;
    uint32_t* Bbase = sm + 2 * BM * ASTRIDE;     // [buf][H/L][128*BSTRIDE]
#define BSH(buf) (Bbase + (buf) * (2 * 128 * BSTRIDE))
#define BSL(buf) (Bbase + (buf) * (2 * 128 * BSTRIDE) + 128 * BSTRIDE)

    const int tid  = threadIdx.x;
    const int wid  = tid >> 5;          // 0..15
    const int lane = tid & 31;
    const int warpM = wid >> 3;         // 0..1 : rows warpM*32..+31
    const int warpN = wid & 7;          // 0..7 : cols warpN*16..+15
    const int blockM = blockIdx.x * BM;

    const float* h = sel_in(in_sel, x);
    float* outp = out_sel == 0 ? ext_out : (out_sel == 1 ? (float*)g_h1 : (float*)g_h2);

    // ---- B chunk loader (512 thr): row = tid>>2 (0..127), 4 floats each ----
    const int bRow = tid >> 2;
    const int bOf  = (tid & 3) << 2;                 // float offset 0/4/8/12
    const int sBaseB = bRow * BSTRIDE + ((tid & 3) << 1);
    float4 pb;
#define LOAD_B(kc) do {                                                        \
        const float* W = ((kc) < 8) ? Wl : Wr;                                 \
        pb = *(const float4*)(W + (size_t)bRow * DD + (((kc) & 7) << 4) + bOf);\
    } while (0)
#define STORE_B(buf) do {                                                      \
        uint32_t lo, hi;                                                       \
        hi = pack_hi_lo(pb.x, pb.y, &lo);                                      \
        BSH(buf)[sBaseB] = hi;     BSL(buf)[sBaseB] = lo;                      \
        hi = pack_hi_lo(pb.z, pb.w, &lo);                                      \
        BSH(buf)[sBaseB + 1] = hi; BSL(buf)[sBaseB + 1] = lo;                  \
    } while (0)

    // issue chunk-0 weight loads now; latency hides behind phase 1
    LOAD_B(0);

    // ---- Phase 1: aggregate 4 nodes per warp + own features -> A tile ----
    for (int i = 0; i < 4; ++i) {
        int r = wid * 4 + i;
        int node = blockM + r;
        float a0 = 0.f, a1 = 0.f, a2 = 0.f, a3 = 0.f;
        float4 own = make_float4(0.f, 0.f, 0.f, 0.f);
        if (node < NN) {
            int beg = g_off[node];
            int end = beg + g_deg[node];
            for (int e = beg; e < end; ++e) {
                int s = g_col[e];
                float4 v = *(((const float4*)(h + (size_t)s * DD)) + lane);
                a0 += v.x; a1 += v.y; a2 += v.z; a3 += v.w;
            }
            float inv = g_invdeg[node];
            a0 *= inv; a1 *= inv; a2 *= inv; a3 *= inv;
            own = *(((const float4*)(h + (size_t)node * DD)) + lane);
        }
        uint32_t lo, hi;
        int base = r * ASTRIDE + lane * 2;
        hi = pack_hi_lo(a0, a1, &lo);     AsH[base] = hi;          AsL[base] = lo;
        hi = pack_hi_lo(a2, a3, &lo);     AsH[base + 1] = hi;      AsL[base + 1] = lo;
        hi = pack_hi_lo(own.x, own.y, &lo); AsH[base + 64] = hi;   AsL[base + 64] = lo;
        hi = pack_hi_lo(own.z, own.w, &lo); AsH[base + 65] = hi;   AsL[base + 65] = lo;
    }
    STORE_B(0);
    __syncthreads();

    // ---- Phase 2: pipelined HMMA over 16 chunks ----
    float acc[2][2][4];
#pragma unroll
    for (int mt = 0; mt < 2; ++mt)
#pragma unroll
        for (int nt = 0; nt < 2; ++nt)
#pragma unroll
            for (int c = 0; c < 4; ++c) acc[mt][nt][c] = 0.f;

    for (int kc = 0; kc < 16; ++kc) {
        const int cur = kc & 1;
        const int nxt = cur ^ 1;
        if (kc < 15) LOAD_B(kc + 1);

        uint32_t ah[2][4], al[2][4];
#pragma unroll
        for (int mt = 0; mt < 2; ++mt) {
            int row = warpM * 32 + mt * 16 + (lane >> 2);
            int base = row * ASTRIDE + kc * 8 + (lane & 3);
            ah[mt][0] = AsH[base];
            ah[mt][1] = AsH[base + 8 * ASTRIDE];
            ah[mt][2] = AsH[base + 4];
            ah[mt][3] = AsH[base + 8 * ASTRIDE + 4];
            al[mt][0] = AsL[base];
            al[mt][1] = AsL[base + 8 * ASTRIDE];
            al[mt][2] = AsL[base + 4];
            al[mt][3] = AsL[base + 8 * ASTRIDE + 4];
        }
        const uint32_t* bH = BSH(cur);
        const uint32_t* bL = BSL(cur);
#pragma unroll
        for (int nt = 0; nt < 2; ++nt) {              // Ah * Bh
            int bb = (warpN * 16 + nt * 8 + (lane >> 2)) * BSTRIDE + (lane & 3);
            uint32_t b0 = bH[bb], b1 = bH[bb + 4];
            mma16816(acc[0][nt], ah[0], b0, b1);
            mma16816(acc[1][nt], ah[1], b0, b1);
        }
#pragma unroll
        for (int nt = 0; nt < 2; ++nt) {              // Ah * Bl
            int bb = (warpN * 16 + nt * 8 + (lane >> 2)) * BSTRIDE + (lane & 3);
            uint32_t b0 = bL[bb], b1 = bL[bb + 4];
            mma16816(acc[0][nt], ah[0], b0, b1);
            mma16816(acc[1][nt], ah[1], b0, b1);
        }
#pragma unroll
        for (int nt = 0; nt < 2; ++nt) {              // Al * Bh
            int bb = (warpN * 16 + nt * 8 + (lane >> 2)) * BSTRIDE + (lane & 3);
            uint32_t b0 = bH[bb], b1 = bH[bb + 4];
            mma16816(acc[0][nt], al[0], b0, b1);
            mma16816(acc[1][nt], al[1], b0, b1);
        }

        if (kc < 15) STORE_B(nxt);
        __syncthreads();
    }

    // ---- epilogue: bias (+relu), float2 stores ----
#pragma unroll
    for (int nt = 0; nt < 2; ++nt) {
        int col = warpN * 16 + nt * 8 + (lane & 3) * 2;
        float2 bb = *(const float2*)(bl + col);
#pragma unroll
        for (int mt = 0; mt < 2; ++mt) {
            int row = blockM + warpM * 32 + mt * 16 + (lane >> 2);
            float* d = acc[mt][nt];
            float2 o0 = make_float2(d[0] + bb.x, d[1] + bb.y);
            float2 o1 = make_float2(d[2] + bb.x, d[3] + bb.y);
            if (relu) {
                o0.x = fmaxf(o0.x, 0.f); o0.y = fmaxf(o0.y, 0.f);
                o1.x = fmaxf(o1.x, 0.f); o1.y = fmaxf(o1.y, 0.f);
            }
            if (row < NN)     *(float2*)(outp + (size_t)row * DD + col) = o0;
            if (row + 8 < NN) *(float2*)(outp + (size_t)(row + 8) * DD + col) = o1;
        }
    }
#undef LOAD_B
#undef STORE_B
#undef BSH
#undef BSL
}

// ---------------- launch (graph-capture safe) ----------------
extern "C" void kernel_launch(void* const* d_in, const int* in_sizes, int n_in,
                              void* d_out, int out_size) {
    const float* x  = (const float*)d_in[0];
    const int*   ei = (const int*)d_in[1];
    const float* Wl1 = (const float*)d_in[2];
    const float* bl1 = (const float*)d_in[3];
    const float* Wr1 = (const float*)d_in[4];
    const float* Wl2 = (const float*)d_in[5];
    const float* bl2 = (const float*)d_in[6];
    const float* Wr2 = (const float*)d_in[7];
    const float* Wl3 = (const float*)d_in[8];
    const float* bl3 = (const float*)d_in[9];
    const float* Wr3 = (const float*)d_in[10];
    float* out = (float*)d_out;

    cudaFuncSetAttribute(k_fused, cudaFuncAttributeMaxDynamicSharedMemorySize, SMEM_BYTES);

    k_detect<<<1, 32>>>(ei);
    k_zero_deg<<<(NN + 255) / 256, 256>>>();
    k_hist<<<(NE + 255) / 256, 256>>>(ei);
    k_alloc<<<(NN + 255) / 256, 256>>>();
    k_fill<<<(NE + 255) / 256, 256>>>(ei);

    const int grid = (NN + BM - 1) / BM;   // 782

    k_fused<<<grid, 512, SMEM_BYTES>>>(0, x, Wl1, bl1, Wr1, 1, out, 1);
    k_fused<<<grid, 512, SMEM_BYTES>>>(1, x, Wl2, bl2, Wr2, 2, out, 0);
    k_fused<<<grid, 512, SMEM_BYTES>>>(2, x, Wl3, bl3, Wr3, 0, out, 0);
}